// round 14
// baseline (speedup 1.0000x reference)
#include <cuda_runtime.h>
#include <cstdint>

#define GG 256
#define NN 512
#define KK 6
#define FF 64
#define PADH 68          // floats per h row (272B, 16B-aligned, bank shift 4)

typedef unsigned long long u64;
typedef unsigned short u16;

// ---------------------------------------------------------------------------
// packed f32x2 helpers
// ---------------------------------------------------------------------------
__device__ __forceinline__ u64 fma2(u64 a, u64 b, u64 c) {
    u64 d;
    asm("fma.rn.f32x2 %0, %1, %2, %3;" : "=l"(d) : "l"(a), "l"(b), "l"(c));
    return d;
}
__device__ __forceinline__ u64 pack2(float lo, float hi) {
    u64 d;
    asm("mov.b64 %0, {%1, %2};" : "=l"(d) : "f"(lo), "f"(hi));
    return d;
}
__device__ __forceinline__ float2 unpack2(u64 v) {
    float lo, hi;
    asm("mov.b64 {%0, %1}, %2;" : "=f"(lo), "=f"(hi) : "l"(v));
    return make_float2(lo, hi);
}

// ---------------------------------------------------------------------------
// smem layout (float offsets). Total 57088 floats = 228352 bytes.
//   h    [0 .. 34816)        : node features, plain, PADH=68 floats/row
//   BIG  [34816 .. 51200)    : knn sq | lin W pair (8192f) | gconv s_tile 256x64
//                              | pool partials / head temps
//   WC   [51200 .. 55296)    : gconv weights (4096f)
//   IDX  [55296 .. 56832)    : knn indices, 512*6 u16
//   BS   [56832 .. 57088)    : biases (b, a pairs)
// ---------------------------------------------------------------------------
#define OF_BIG 34816
#define OF_WC  51200
#define OF_IDX 55296
#define OF_BS  56832
#define SMEM_FLOATS 57088
#define SMEM_BYTES (SMEM_FLOATS * 4)

// ---------------------------------------------------------------------------
// mm over a 256-row tile: 512 threads; rg = tid>>4 (8 rows), cg4 = tid&15.
// Odd-rg half-warps iterate rows in r^4 order (bank-conflict-free vs even rg:
// row distance == 4 mod 8 -> 16-bank offset at PAD=68). acc[r] always maps to
// row rg*8+r, so epilogues and per-element accumulation order are unchanged.
// ---------------------------------------------------------------------------
template<int PAD>
__device__ __forceinline__ void mm256(const float* __restrict__ xs,
                                      const float* __restrict__ Ws,
                                      u64 (&acc)[8][2], int rowbase, int rg, int cg4)
{
    const int cg = cg4 * 4;
    const int stag = (rg & 1) << 2;
    #pragma unroll
    for (int r = 0; r < 8; r++) { acc[r][0] = 0ull; acc[r][1] = 0ull; }
    #pragma unroll 2
    for (int kc4 = 0; kc4 < 16; kc4++) {
        const int k0 = kc4 * 4;
        const ulonglong2 w0 = *(const ulonglong2*)&Ws[(k0+0)*64 + cg];
        const ulonglong2 w1 = *(const ulonglong2*)&Ws[(k0+1)*64 + cg];
        const ulonglong2 w2 = *(const ulonglong2*)&Ws[(k0+2)*64 + cg];
        const ulonglong2 w3 = *(const ulonglong2*)&Ws[(k0+3)*64 + cg];
        #pragma unroll
        for (int r0 = 0; r0 < 8; r0++) {
            const int r = r0 ^ stag;
            const float4 xv = *(const float4*)&xs[(rowbase + rg*8 + r)*PAD + k0];
            const u64 x0 = pack2(xv.x, xv.x);
            const u64 x1 = pack2(xv.y, xv.y);
            const u64 x2 = pack2(xv.z, xv.z);
            const u64 x3 = pack2(xv.w, xv.w);
            acc[r][0] = fma2(x0, w0.x, acc[r][0]);
            acc[r][1] = fma2(x0, w0.y, acc[r][1]);
            acc[r][0] = fma2(x1, w1.x, acc[r][0]);
            acc[r][1] = fma2(x1, w1.y, acc[r][1]);
            acc[r][0] = fma2(x2, w2.x, acc[r][0]);
            acc[r][1] = fma2(x2, w2.y, acc[r][1]);
            acc[r][0] = fma2(x3, w3.x, acc[r][0]);
            acc[r][1] = fma2(x3, w3.y, acc[r][1]);
        }
    }
}

// lin layer: h = prelu(h @ W + b), in place, 2 tiles of 256 rows.
// Rows rg*8.. are touched ONLY by the owning half-warp -> warp syncs suffice.
__device__ __forceinline__ void lin_layer(float* __restrict__ sm,
                                          const float* __restrict__ Ws,
                                          const float* __restrict__ BS, int boff,
                                          int rg, int cg4)
{
    float4* h4 = (float4*)sm;
    const int cg = cg4 * 4;
    u64 acc[8][2];
    #pragma unroll 1
    for (int tile = 0; tile < 2; tile++) {
        mm256<PADH>(sm, Ws, acc, tile * 256, rg, cg4);
        __syncwarp();
        #pragma unroll
        for (int r = 0; r < 8; r++) {
            const int row = tile*256 + rg*8 + r;
            const float2 p0 = unpack2(acc[r][0]);
            const float2 p1 = unpack2(acc[r][1]);
            float4 o; float v;
            v = p0.x + BS[boff+cg+0]; o.x = (v >= 0.f) ? v : v * BS[boff+64+cg+0];
            v = p0.y + BS[boff+cg+1]; o.y = (v >= 0.f) ? v : v * BS[boff+64+cg+1];
            v = p1.x + BS[boff+cg+2]; o.z = (v >= 0.f) ? v : v * BS[boff+64+cg+2];
            v = p1.y + BS[boff+cg+3]; o.w = (v >= 0.f) ? v : v * BS[boff+64+cg+3];
            h4[row*17 + cg4] = o;
        }
        __syncwarp();
    }
}

// gather neighbor sums for half H (rows H*256 .. H*256+255) into s_tile (64/row)
__device__ __forceinline__ void gather_half(const float* __restrict__ sm,
                                            float* __restrict__ sT,
                                            const u16* __restrict__ IDX,
                                            int H, int tid)
{
    const float4* h4 = (const float4*)sm;
    float4* s4 = (float4*)sT;
    const int r_l = tid >> 1;
    const int fh = tid & 1;
    const int row = H*256 + r_l;
    const u16* ip = IDX + row * KK;
    float4 a[8];
    {
        const int j = ip[0];
        #pragma unroll
        for (int c = 0; c < 8; c++) a[c] = h4[j*17 + fh*8 + c];
    }
    #pragma unroll
    for (int n = 1; n < KK; n++) {
        const int j = ip[n];
        #pragma unroll
        for (int c = 0; c < 8; c++) {
            const float4 v = h4[j*17 + fh*8 + c];
            a[c].x += v.x; a[c].y += v.y; a[c].z += v.z; a[c].w += v.w;
        }
    }
    #pragma unroll
    for (int c = 0; c < 8; c++) s4[r_l*16 + fh*8 + c] = a[c];
}

// gconv epilogue: h[row] = acc + 6*b + h[row] (residual), rows of half H
__device__ __forceinline__ void gconv_write(float* __restrict__ sm,
                                            const float* __restrict__ BS,
                                            u64 (&acc)[8][2], int H, int rg, int cg4)
{
    float4* h4 = (float4*)sm;
    const int cg = cg4 * 4;
    #pragma unroll
    for (int r = 0; r < 8; r++) {
        const int row = H*256 + rg*8 + r;
        const float4 hres = h4[row*17 + cg4];
        const float2 p0 = unpack2(acc[r][0]);
        const float2 p1 = unpack2(acc[r][1]);
        float4 o;
        o.x = p0.x + 6.f*BS[cg+0] + hres.x;
        o.y = p0.y + 6.f*BS[cg+1] + hres.y;
        o.z = p1.x + 6.f*BS[cg+2] + hres.z;
        o.w = p1.y + 6.f*BS[cg+3] + hres.w;
        h4[row*17 + cg4] = o;
    }
}

// ===========================================================================
// Mega kernel: whole network, one block per graph, 512 threads.
// ===========================================================================
__global__ void __launch_bounds__(512, 1) mega_kernel(
    const float* __restrict__ x,
    const float* __restrict__ W1, const float* __restrict__ b1, const float* __restrict__ a1,
    const float* __restrict__ W2, const float* __restrict__ b2, const float* __restrict__ a2,
    const float* __restrict__ Wc1, const float* __restrict__ bc1,
    const float* __restrict__ Wc2, const float* __restrict__ bc2,
    const float* __restrict__ Wc3, const float* __restrict__ bc3,
    const float* __restrict__ Wc4, const float* __restrict__ bc4,
    const float* __restrict__ W3, const float* __restrict__ b3, const float* __restrict__ a3,
    const float* __restrict__ W4, const float* __restrict__ b4, const float* __restrict__ a4,
    const float* __restrict__ Wh1, const float* __restrict__ bh1,
    const float* __restrict__ Wh2, const float* __restrict__ bh2,
    const float* __restrict__ Wh3, const float* __restrict__ bh3,
    const float* __restrict__ Wh4, const float* __restrict__ bh4,
    float* __restrict__ out)
{
    extern __shared__ float sm[];
    float4* h4 = (float4*)sm;
    float* BIG = sm + OF_BIG;
    float* WC  = sm + OF_WC;
    u16*   IDX = (u16*)(sm + OF_IDX);
    float* BS  = sm + OF_BS;

    const int tid = threadIdx.x;
    const int g   = blockIdx.x;
    const int rg  = tid >> 4;
    const int cg4 = tid & 15;
    const float4* xg4 = (const float4*)(x + (size_t)g * NN * FF);

    // ---- load x -> h (plain, padded) ----
    #pragma unroll
    for (int c = 0, i = tid; c < 16; c++, i += 512) {
        const int row = i >> 4, c4 = i & 15;
        h4[row*17 + c4] = xg4[i];
    }
    __syncthreads();

    // ---- sq (k-ascending, R4-identical accumulation) ----
    {
        const int row = tid;
        float s = 0.f;
        #pragma unroll
        for (int c4 = 0; c4 < 16; c4++) {
            const float4 v = h4[row*17 + c4];
            s += v.x*v.x + v.y*v.y + v.z*v.z + v.w*v.w;
        }
        BIG[row] = s;   // sq lives in BIG during knn
    }
    __syncthreads();

    // ---- kNN: 1 query per thread, FFMA2 dots (4 chains), strict-< top-6 ----
    {
        const int q = tid;
        u64 xq[32];
        #pragma unroll
        for (int c4 = 0; c4 < 16; c4++) {
            const ulonglong2 v = *(const ulonglong2*)&sm[q*PADH + c4*4];
            xq[2*c4] = v.x; xq[2*c4+1] = v.y;
        }
        const float sqq = BIG[q];
        float bd[6]; int bi[6];
        #pragma unroll
        for (int t = 0; t < 6; t++) { bd[t] = 3.0e38f; bi[t] = 0; }
        float wv = 3.0e38f; int ws = 0;

        const float* cjp = sm;
        for (int j = 0; j < NN; j++, cjp += PADH) {
            u64 a = 0ull, b = 0ull, cch = 0ull, dch = 0ull;
            #pragma unroll
            for (int c4 = 0; c4 < 16; c4 += 2) {
                const ulonglong2 v0 = *(const ulonglong2*)&cjp[c4*4];
                const ulonglong2 v1 = *(const ulonglong2*)&cjp[c4*4 + 4];
                a   = fma2(xq[2*c4],   v0.x, a);
                b   = fma2(xq[2*c4+1], v0.y, b);
                cch = fma2(xq[2*c4+2], v1.x, cch);
                dch = fma2(xq[2*c4+3], v1.y, dch);
            }
            const float2 fa = unpack2(a), fb = unpack2(b);
            const float2 fc = unpack2(cch), fd = unpack2(dch);
            const float dot = ((fa.x + fa.y) + (fb.x + fb.y))
                            + ((fc.x + fc.y) + (fd.x + fd.y));
            const float d = __fsub_rn(sqq + BIG[j], __fmul_rn(2.f, dot));
            if (j != q && d < wv) {
                bd[ws] = d; bi[ws] = j;
                wv = bd[0]; ws = 0;
                #pragma unroll
                for (int t = 1; t < 6; t++) if (bd[t] > wv) { wv = bd[t]; ws = t; }
            }
        }
        #pragma unroll
        for (int t = 0; t < 6; t++) IDX[q*KK + t] = (u16)bi[t];
    }
    __syncthreads();

    // ---- lin1 + lin2 (weights into BIG; sq dead). 1024 float4 per matrix. ----
    {
        #pragma unroll
        for (int c = 0, i = tid; c < 2; c++, i += 512) {
            ((float4*)BIG)[i]        = ((const float4*)W1)[i];
            ((float4*)BIG)[1024 + i] = ((const float4*)W2)[i];
        }
        if (tid < 64) { BS[tid] = b1[tid]; BS[64+tid] = a1[tid]; BS[128+tid] = b2[tid]; BS[192+tid] = a2[tid]; }
        __syncthreads();
        lin_layer(sm, BIG,        BS, 0,   rg, cg4);
        lin_layer(sm, BIG + 4096, BS, 128, rg, cg4);
        __syncthreads();   // all h writes visible before gconv gathers
    }

    // ---- 4 x gconv ----
    const float* Wcs[4] = {Wc1, Wc2, Wc3, Wc4};
    const float* bcs[4] = {bc1, bc2, bc3, bc4};
    #pragma unroll 1
    for (int L = 0; L < 4; L++) {
        #pragma unroll
        for (int c = 0, i = tid; c < 2; c++, i += 512)
            ((float4*)WC)[i] = ((const float4*)Wcs[L])[i];
        if (tid < 64) BS[tid] = bcs[L][tid];
        __syncthreads();

        u64 accA[8][2], accB[8][2];
        gather_half(sm, BIG, IDX, 0, tid);      // s_tile <- sums rows 0..255 (reads old h)
        __syncthreads();
        mm256<64>(BIG, WC, accA, 0, rg, cg4);
        __syncthreads();                        // s reads done before overwrite
        gather_half(sm, BIG, IDX, 1, tid);      // s_tile <- sums rows 256..511 (old h)
        __syncthreads();                        // all h reads done
        gconv_write(sm, BS, accA, 0, rg, cg4);  // overwrite h rows 0..255
        mm256<64>(BIG, WC, accB, 0, rg, cg4);
        gconv_write(sm, BS, accB, 1, rg, cg4);  // overwrite h rows 256..511
        __syncthreads();
    }

    // ---- lin3 + lin4 ----
    {
        #pragma unroll
        for (int c = 0, i = tid; c < 2; c++, i += 512) {
            ((float4*)BIG)[i]        = ((const float4*)W3)[i];
            ((float4*)BIG)[1024 + i] = ((const float4*)W4)[i];
        }
        if (tid < 64) { BS[tid] = b3[tid]; BS[64+tid] = a3[tid]; BS[128+tid] = b4[tid]; BS[192+tid] = a4[tid]; }
        __syncthreads();
        lin_layer(sm, BIG,        BS, 0,   rg, cg4);
        lin_layer(sm, BIG + 4096, BS, 128, rg, cg4);
        __syncthreads();   // all h writes visible before pool
    }

    // ---- pool: column sums of h over 512 rows (8 segments x 64 rows) ----
    {
        const int c = tid & 63, seg = tid >> 6;
        float s = 0.f;
        #pragma unroll 4
        for (int r2 = 0; r2 < 64; r2++) {
            const int row = seg*64 + r2;
            s += sm[row*PADH + c];
        }
        BIG[1024 + seg*64 + c] = s;
    }
    __syncthreads();
    if (tid < 64) {
        float ps = 0.f;
        #pragma unroll
        for (int seg = 0; seg < 8; seg++) ps += BIG[1024 + seg*64 + tid];
        BIG[1536 + tid] = ps;     // pooled[64]
    }
    __syncthreads();

    // ---- head MLP: 64 -> 256 -> 256 -> 64 -> 1 (leaky 0.2) ----
    {
        float* pooled = BIG + 1536;
        float* y1 = BIG;          // [0..256)
        float* y2 = BIG + 256;    // [256..512)
        float* y3 = BIG + 512;    // [512..576)
        if (tid < 256) {
            float v = bh1[tid];
            #pragma unroll 4
            for (int k = 0; k < 64; k++) v = fmaf(pooled[k], Wh1[k*256 + tid], v);
            y1[tid] = (v >= 0.f) ? v : 0.2f * v;
        }
        __syncthreads();
        if (tid < 256) {
            float v = bh2[tid];
            #pragma unroll 4
            for (int k = 0; k < 256; k++) v = fmaf(y1[k], Wh2[k*256 + tid], v);
            y2[tid] = (v >= 0.f) ? v : 0.2f * v;
        }
        __syncthreads();
        if (tid < 64) {
            float v = bh3[tid];
            #pragma unroll 4
            for (int k = 0; k < 256; k++) v = fmaf(y2[k], Wh3[k*64 + tid], v);
            y3[tid] = (v >= 0.f) ? v : 0.2f * v;
        }
        __syncthreads();
        if (tid == 0) {
            float v = bh4[0];
            #pragma unroll
            for (int k = 0; k < 64; k++) v = fmaf(y3[k], Wh4[k], v);
            out[g] = v;
        }
    }
}

// ---------------------------------------------------------------------------
extern "C" void kernel_launch(void* const* d_in, const int* in_sizes, int n_in,
                              void* d_out, int out_size)
{
    const float* x   = (const float*)d_in[0];
    const float* W1  = (const float*)d_in[1];
    const float* b1  = (const float*)d_in[2];
    const float* a1  = (const float*)d_in[3];
    const float* W2  = (const float*)d_in[4];
    const float* b2  = (const float*)d_in[5];
    const float* a2  = (const float*)d_in[6];
    const float* Wc1 = (const float*)d_in[7];
    const float* bc1 = (const float*)d_in[8];
    const float* Wc2 = (const float*)d_in[9];
    const float* bc2 = (const float*)d_in[10];
    const float* Wc3 = (const float*)d_in[11];
    const float* bc3 = (const float*)d_in[12];
    const float* Wc4 = (const float*)d_in[13];
    const float* bc4 = (const float*)d_in[14];
    const float* W3  = (const float*)d_in[15];
    const float* b3  = (const float*)d_in[16];
    const float* a3  = (const float*)d_in[17];
    const float* W4  = (const float*)d_in[18];
    const float* b4  = (const float*)d_in[19];
    const float* a4  = (const float*)d_in[20];
    const float* Wh1 = (const float*)d_in[21];
    const float* bh1 = (const float*)d_in[22];
    const float* Wh2 = (const float*)d_in[23];
    const float* bh2 = (const float*)d_in[24];
    const float* Wh3 = (const float*)d_in[25];
    const float* bh3 = (const float*)d_in[26];
    const float* Wh4 = (const float*)d_in[27];
    const float* bh4 = (const float*)d_in[28];
    float* out = (float*)d_out;

    cudaFuncSetAttribute(mega_kernel, cudaFuncAttributeMaxDynamicSharedMemorySize, SMEM_BYTES);
    mega_kernel<<<GG, 512, SMEM_BYTES>>>(
        x, W1, b1, a1, W2, b2, a2,
        Wc1, bc1, Wc2, bc2, Wc3, bc3, Wc4, bc4,
        W3, b3, a3, W4, b4, a4,
        Wh1, bh1, Wh2, bh2, Wh3, bh3, Wh4, bh4, out);
}

// round 15
// speedup vs baseline: 1.2303x; 1.2303x over previous
#include <cuda_runtime.h>
#include <cstdint>

#define GG 256
#define NN 512
#define KK 6
#define FF 64
#define PADH 68          // floats per h row (272B, 16B-aligned, bank shift 4)

typedef unsigned long long u64;
typedef unsigned short u16;

// ---------------------------------------------------------------------------
// packed f32x2 helpers
// ---------------------------------------------------------------------------
__device__ __forceinline__ u64 fma2(u64 a, u64 b, u64 c) {
    u64 d;
    asm("fma.rn.f32x2 %0, %1, %2, %3;" : "=l"(d) : "l"(a), "l"(b), "l"(c));
    return d;
}
__device__ __forceinline__ u64 pack2(float lo, float hi) {
    u64 d;
    asm("mov.b64 %0, {%1, %2};" : "=l"(d) : "f"(lo), "f"(hi));
    return d;
}
__device__ __forceinline__ float2 unpack2(u64 v) {
    float lo, hi;
    asm("mov.b64 {%0, %1}, %2;" : "=f"(lo), "=f"(hi) : "l"(v));
    return make_float2(lo, hi);
}

// ---------------------------------------------------------------------------
// smem layout (float offsets). Total 57088 floats = 228352 bytes.
//   h    [0 .. 34816)        : node features, plain, PADH=68 floats/row
//   BIG  [34816 .. 51200)    : knn sq | lin W pair (8192f) | gconv s_tile 256x64
//                              | pool partials / head temps
//   WC   [51200 .. 55296)    : gconv weights (4096f)
//   IDX  [55296 .. 56832)    : knn indices, 512*6 u16
//   BS   [56832 .. 57088)    : biases (b, a pairs)
// ---------------------------------------------------------------------------
#define OF_BIG 34816
#define OF_WC  51200
#define OF_IDX 55296
#define OF_BS  56832
#define SMEM_FLOATS 57088
#define SMEM_BYTES (SMEM_FLOATS * 4)

// ---------------------------------------------------------------------------
// mm over a 256-row tile: 512 threads; rg = tid>>4 (8 rows), cg4 = tid&15.
// Plain r-ascending row order: acc[] indices are compile-time constants so
// the accumulators stay in registers (dynamic indexing spills to local).
// ---------------------------------------------------------------------------
template<int PAD>
__device__ __forceinline__ void mm256(const float* __restrict__ xs,
                                      const float* __restrict__ Ws,
                                      u64 (&acc)[8][2], int rowbase, int rg, int cg4)
{
    const int cg = cg4 * 4;
    #pragma unroll
    for (int r = 0; r < 8; r++) { acc[r][0] = 0ull; acc[r][1] = 0ull; }
    #pragma unroll 2
    for (int kc4 = 0; kc4 < 16; kc4++) {
        const int k0 = kc4 * 4;
        const ulonglong2 w0 = *(const ulonglong2*)&Ws[(k0+0)*64 + cg];
        const ulonglong2 w1 = *(const ulonglong2*)&Ws[(k0+1)*64 + cg];
        const ulonglong2 w2 = *(const ulonglong2*)&Ws[(k0+2)*64 + cg];
        const ulonglong2 w3 = *(const ulonglong2*)&Ws[(k0+3)*64 + cg];
        #pragma unroll
        for (int r = 0; r < 8; r++) {
            const float4 xv = *(const float4*)&xs[(rowbase + rg*8 + r)*PAD + k0];
            const u64 x0 = pack2(xv.x, xv.x);
            const u64 x1 = pack2(xv.y, xv.y);
            const u64 x2 = pack2(xv.z, xv.z);
            const u64 x3 = pack2(xv.w, xv.w);
            acc[r][0] = fma2(x0, w0.x, acc[r][0]);
            acc[r][1] = fma2(x0, w0.y, acc[r][1]);
            acc[r][0] = fma2(x1, w1.x, acc[r][0]);
            acc[r][1] = fma2(x1, w1.y, acc[r][1]);
            acc[r][0] = fma2(x2, w2.x, acc[r][0]);
            acc[r][1] = fma2(x2, w2.y, acc[r][1]);
            acc[r][0] = fma2(x3, w3.x, acc[r][0]);
            acc[r][1] = fma2(x3, w3.y, acc[r][1]);
        }
    }
}

// lin layer: h = prelu(h @ W + b), in place, 2 tiles of 256 rows.
// Rows rg*8.. are touched ONLY by the owning half-warp -> warp syncs suffice.
__device__ __forceinline__ void lin_layer(float* __restrict__ sm,
                                          const float* __restrict__ Ws,
                                          const float* __restrict__ BS, int boff,
                                          int rg, int cg4)
{
    float4* h4 = (float4*)sm;
    const int cg = cg4 * 4;
    u64 acc[8][2];
    #pragma unroll 1
    for (int tile = 0; tile < 2; tile++) {
        mm256<PADH>(sm, Ws, acc, tile * 256, rg, cg4);
        __syncwarp();
        #pragma unroll
        for (int r = 0; r < 8; r++) {
            const int row = tile*256 + rg*8 + r;
            const float2 p0 = unpack2(acc[r][0]);
            const float2 p1 = unpack2(acc[r][1]);
            float4 o; float v;
            v = p0.x + BS[boff+cg+0]; o.x = (v >= 0.f) ? v : v * BS[boff+64+cg+0];
            v = p0.y + BS[boff+cg+1]; o.y = (v >= 0.f) ? v : v * BS[boff+64+cg+1];
            v = p1.x + BS[boff+cg+2]; o.z = (v >= 0.f) ? v : v * BS[boff+64+cg+2];
            v = p1.y + BS[boff+cg+3]; o.w = (v >= 0.f) ? v : v * BS[boff+64+cg+3];
            h4[row*17 + cg4] = o;
        }
        __syncwarp();
    }
}

// gather neighbor sums for half H (rows H*256 .. H*256+255) into s_tile (64/row)
__device__ __forceinline__ void gather_half(const float* __restrict__ sm,
                                            float* __restrict__ sT,
                                            const u16* __restrict__ IDX,
                                            int H, int tid)
{
    const float4* h4 = (const float4*)sm;
    float4* s4 = (float4*)sT;
    const int r_l = tid >> 1;
    const int fh = tid & 1;
    const int row = H*256 + r_l;
    const u16* ip = IDX + row * KK;
    float4 a[8];
    {
        const int j = ip[0];
        #pragma unroll
        for (int c = 0; c < 8; c++) a[c] = h4[j*17 + fh*8 + c];
    }
    #pragma unroll
    for (int n = 1; n < KK; n++) {
        const int j = ip[n];
        #pragma unroll
        for (int c = 0; c < 8; c++) {
            const float4 v = h4[j*17 + fh*8 + c];
            a[c].x += v.x; a[c].y += v.y; a[c].z += v.z; a[c].w += v.w;
        }
    }
    #pragma unroll
    for (int c = 0; c < 8; c++) s4[r_l*16 + fh*8 + c] = a[c];
}

// gconv epilogue: h[row] = acc + 6*b + h[row] (residual), rows of half H
__device__ __forceinline__ void gconv_write(float* __restrict__ sm,
                                            const float* __restrict__ BS,
                                            u64 (&acc)[8][2], int H, int rg, int cg4)
{
    float4* h4 = (float4*)sm;
    const int cg = cg4 * 4;
    #pragma unroll
    for (int r = 0; r < 8; r++) {
        const int row = H*256 + rg*8 + r;
        const float4 hres = h4[row*17 + cg4];
        const float2 p0 = unpack2(acc[r][0]);
        const float2 p1 = unpack2(acc[r][1]);
        float4 o;
        o.x = p0.x + 6.f*BS[cg+0] + hres.x;
        o.y = p0.y + 6.f*BS[cg+1] + hres.y;
        o.z = p1.x + 6.f*BS[cg+2] + hres.z;
        o.w = p1.y + 6.f*BS[cg+3] + hres.w;
        h4[row*17 + cg4] = o;
    }
}

// ===========================================================================
// Mega kernel: whole network, one block per graph, 512 threads.
// ===========================================================================
__global__ void __launch_bounds__(512, 1) mega_kernel(
    const float* __restrict__ x,
    const float* __restrict__ W1, const float* __restrict__ b1, const float* __restrict__ a1,
    const float* __restrict__ W2, const float* __restrict__ b2, const float* __restrict__ a2,
    const float* __restrict__ Wc1, const float* __restrict__ bc1,
    const float* __restrict__ Wc2, const float* __restrict__ bc2,
    const float* __restrict__ Wc3, const float* __restrict__ bc3,
    const float* __restrict__ Wc4, const float* __restrict__ bc4,
    const float* __restrict__ W3, const float* __restrict__ b3, const float* __restrict__ a3,
    const float* __restrict__ W4, const float* __restrict__ b4, const float* __restrict__ a4,
    const float* __restrict__ Wh1, const float* __restrict__ bh1,
    const float* __restrict__ Wh2, const float* __restrict__ bh2,
    const float* __restrict__ Wh3, const float* __restrict__ bh3,
    const float* __restrict__ Wh4, const float* __restrict__ bh4,
    float* __restrict__ out)
{
    extern __shared__ float sm[];
    float4* h4 = (float4*)sm;
    float* BIG = sm + OF_BIG;
    float* WC  = sm + OF_WC;
    u16*   IDX = (u16*)(sm + OF_IDX);
    float* BS  = sm + OF_BS;

    const int tid = threadIdx.x;
    const int g   = blockIdx.x;
    const int rg  = tid >> 4;
    const int cg4 = tid & 15;
    const float4* xg4 = (const float4*)(x + (size_t)g * NN * FF);

    // ---- load x -> h (plain, padded) ----
    #pragma unroll
    for (int c = 0, i = tid; c < 16; c++, i += 512) {
        const int row = i >> 4, c4 = i & 15;
        h4[row*17 + c4] = xg4[i];
    }
    __syncthreads();

    // ---- sq (k-ascending, R4-identical accumulation) ----
    {
        const int row = tid;
        float s = 0.f;
        #pragma unroll
        for (int c4 = 0; c4 < 16; c4++) {
            const float4 v = h4[row*17 + c4];
            s += v.x*v.x + v.y*v.y + v.z*v.z + v.w*v.w;
        }
        BIG[row] = s;   // sq lives in BIG during knn
    }
    __syncthreads();

    // ---- kNN: 1 query per thread, FFMA2 dots (4 chains), strict-< top-6 ----
    {
        const int q = tid;
        u64 xq[32];
        #pragma unroll
        for (int c4 = 0; c4 < 16; c4++) {
            const ulonglong2 v = *(const ulonglong2*)&sm[q*PADH + c4*4];
            xq[2*c4] = v.x; xq[2*c4+1] = v.y;
        }
        const float sqq = BIG[q];
        float bd[6]; int bi[6];
        #pragma unroll
        for (int t = 0; t < 6; t++) { bd[t] = 3.0e38f; bi[t] = 0; }
        float wv = 3.0e38f; int ws = 0;

        const float* cjp = sm;
        for (int j = 0; j < NN; j++, cjp += PADH) {
            u64 a = 0ull, b = 0ull, cch = 0ull, dch = 0ull;
            #pragma unroll
            for (int c4 = 0; c4 < 16; c4 += 2) {
                const ulonglong2 v0 = *(const ulonglong2*)&cjp[c4*4];
                const ulonglong2 v1 = *(const ulonglong2*)&cjp[c4*4 + 4];
                a   = fma2(xq[2*c4],   v0.x, a);
                b   = fma2(xq[2*c4+1], v0.y, b);
                cch = fma2(xq[2*c4+2], v1.x, cch);
                dch = fma2(xq[2*c4+3], v1.y, dch);
            }
            const float2 fa = unpack2(a), fb = unpack2(b);
            const float2 fc = unpack2(cch), fd = unpack2(dch);
            const float dot = ((fa.x + fa.y) + (fb.x + fb.y))
                            + ((fc.x + fc.y) + (fd.x + fd.y));
            const float d = __fsub_rn(sqq + BIG[j], __fmul_rn(2.f, dot));
            if (j != q && d < wv) {
                bd[ws] = d; bi[ws] = j;
                wv = bd[0]; ws = 0;
                #pragma unroll
                for (int t = 1; t < 6; t++) if (bd[t] > wv) { wv = bd[t]; ws = t; }
            }
        }
        #pragma unroll
        for (int t = 0; t < 6; t++) IDX[q*KK + t] = (u16)bi[t];
    }
    __syncthreads();

    // ---- lin1 + lin2 (weights into BIG; sq dead). 1024 float4 per matrix. ----
    {
        #pragma unroll
        for (int c = 0, i = tid; c < 2; c++, i += 512) {
            ((float4*)BIG)[i]        = ((const float4*)W1)[i];
            ((float4*)BIG)[1024 + i] = ((const float4*)W2)[i];
        }
        if (tid < 64) { BS[tid] = b1[tid]; BS[64+tid] = a1[tid]; BS[128+tid] = b2[tid]; BS[192+tid] = a2[tid]; }
        __syncthreads();
        lin_layer(sm, BIG,        BS, 0,   rg, cg4);
        lin_layer(sm, BIG + 4096, BS, 128, rg, cg4);
        __syncthreads();   // all h writes visible before gconv gathers
    }

    // ---- 4 x gconv ----
    const float* Wcs[4] = {Wc1, Wc2, Wc3, Wc4};
    const float* bcs[4] = {bc1, bc2, bc3, bc4};
    #pragma unroll 1
    for (int L = 0; L < 4; L++) {
        #pragma unroll
        for (int c = 0, i = tid; c < 2; c++, i += 512)
            ((float4*)WC)[i] = ((const float4*)Wcs[L])[i];
        if (tid < 64) BS[tid] = bcs[L][tid];
        __syncthreads();

        u64 accA[8][2], accB[8][2];
        gather_half(sm, BIG, IDX, 0, tid);      // s_tile <- sums rows 0..255 (reads old h)
        __syncthreads();
        mm256<64>(BIG, WC, accA, 0, rg, cg4);
        __syncthreads();                        // s reads done before overwrite
        gather_half(sm, BIG, IDX, 1, tid);      // s_tile <- sums rows 256..511 (old h)
        __syncthreads();                        // all h reads done
        gconv_write(sm, BS, accA, 0, rg, cg4);  // overwrite h rows 0..255
        mm256<64>(BIG, WC, accB, 0, rg, cg4);
        gconv_write(sm, BS, accB, 1, rg, cg4);  // overwrite h rows 256..511
        __syncthreads();
    }

    // ---- lin3 + lin4 ----
    {
        #pragma unroll
        for (int c = 0, i = tid; c < 2; c++, i += 512) {
            ((float4*)BIG)[i]        = ((const float4*)W3)[i];
            ((float4*)BIG)[1024 + i] = ((const float4*)W4)[i];
        }
        if (tid < 64) { BS[tid] = b3[tid]; BS[64+tid] = a3[tid]; BS[128+tid] = b4[tid]; BS[192+tid] = a4[tid]; }
        __syncthreads();
        lin_layer(sm, BIG,        BS, 0,   rg, cg4);
        lin_layer(sm, BIG + 4096, BS, 128, rg, cg4);
        __syncthreads();   // all h writes visible before pool
    }

    // ---- pool: column sums of h over 512 rows (8 segments x 64 rows) ----
    {
        const int c = tid & 63, seg = tid >> 6;
        float s = 0.f;
        #pragma unroll 4
        for (int r2 = 0; r2 < 64; r2++) {
            const int row = seg*64 + r2;
            s += sm[row*PADH + c];
        }
        BIG[1024 + seg*64 + c] = s;
    }
    __syncthreads();
    if (tid < 64) {
        float ps = 0.f;
        #pragma unroll
        for (int seg = 0; seg < 8; seg++) ps += BIG[1024 + seg*64 + tid];
        BIG[1536 + tid] = ps;     // pooled[64]
    }
    __syncthreads();

    // ---- head MLP: 64 -> 256 -> 256 -> 64 -> 1 (leaky 0.2) ----
    {
        float* pooled = BIG + 1536;
        float* y1 = BIG;          // [0..256)
        float* y2 = BIG + 256;    // [256..512)
        float* y3 = BIG + 512;    // [512..576)
        if (tid < 256) {
            float v = bh1[tid];
            #pragma unroll 4
            for (int k = 0; k < 64; k++) v = fmaf(pooled[k], Wh1[k*256 + tid], v);
            y1[tid] = (v >= 0.f) ? v : 0.2f * v;
        }
        __syncthreads();
        if (tid < 256) {
            float v = bh2[tid];
            #pragma unroll 4
            for (int k = 0; k < 256; k++) v = fmaf(y1[k], Wh2[k*256 + tid], v);
            y2[tid] = (v >= 0.f) ? v : 0.2f * v;
        }
        __syncthreads();
        if (tid < 64) {
            float v = bh3[tid];
            #pragma unroll 4
            for (int k = 0; k < 256; k++) v = fmaf(y2[k], Wh3[k*64 + tid], v);
            y3[tid] = (v >= 0.f) ? v : 0.2f * v;
        }
        __syncthreads();
        if (tid == 0) {
            float v = bh4[0];
            #pragma unroll
            for (int k = 0; k < 64; k++) v = fmaf(y3[k], Wh4[k], v);
            out[g] = v;
        }
    }
}

// ---------------------------------------------------------------------------
extern "C" void kernel_launch(void* const* d_in, const int* in_sizes, int n_in,
                              void* d_out, int out_size)
{
    const float* x   = (const float*)d_in[0];
    const float* W1  = (const float*)d_in[1];
    const float* b1  = (const float*)d_in[2];
    const float* a1  = (const float*)d_in[3];
    const float* W2  = (const float*)d_in[4];
    const float* b2  = (const float*)d_in[5];
    const float* a2  = (const float*)d_in[6];
    const float* Wc1 = (const float*)d_in[7];
    const float* bc1 = (const float*)d_in[8];
    const float* Wc2 = (const float*)d_in[9];
    const float* bc2 = (const float*)d_in[10];
    const float* Wc3 = (const float*)d_in[11];
    const float* bc3 = (const float*)d_in[12];
    const float* Wc4 = (const float*)d_in[13];
    const float* bc4 = (const float*)d_in[14];
    const float* W3  = (const float*)d_in[15];
    const float* b3  = (const float*)d_in[16];
    const float* a3  = (const float*)d_in[17];
    const float* W4  = (const float*)d_in[18];
    const float* b4  = (const float*)d_in[19];
    const float* a4  = (const float*)d_in[20];
    const float* Wh1 = (const float*)d_in[21];
    const float* bh1 = (const float*)d_in[22];
    const float* Wh2 = (const float*)d_in[23];
    const float* bh2 = (const float*)d_in[24];
    const float* Wh3 = (const float*)d_in[25];
    const float* bh3 = (const float*)d_in[26];
    const float* Wh4 = (const float*)d_in[27];
    const float* bh4 = (const float*)d_in[28];
    float* out = (float*)d_out;

    cudaFuncSetAttribute(mega_kernel, cudaFuncAttributeMaxDynamicSharedMemorySize, SMEM_BYTES);
    mega_kernel<<<GG, 512, SMEM_BYTES>>>(
        x, W1, b1, a1, W2, b2, a2,
        Wc1, bc1, Wc2, bc2, Wc3, bc3, Wc4, bc4,
        W3, b3, a3, W4, b4, a4,
        Wh1, bh1, Wh2, bh2, Wh3, bh3, Wh4, bh4, out);
}